// round 14
// baseline (speedup 1.0000x reference)
#include <cuda_runtime.h>
#include <math.h>
#include <stdint.h>

// ---------------- problem constants ----------------
#define BATCH 8
#define CDIM 192
#define HH 64
#define WW 64
#define LTOK 4096
#define TOK 32768
#define HEADS 6
#define HD 32
#define WS 8
#define NW 64
#define NWIN 512
#define INCC 16
#define HID 768

// ---------------- scratch (all token-major tensors in WINDOW-MAJOR row order) --
__device__ float g_shortcut[TOK * CDIM];
__device__ float g_qkv[TOK * 3 * CDIM];
__device__ float g_attnout[TOK * CDIM];
__device__ float g_x2[TOK * CDIM];
__device__ float g_ln2[TOK * CDIM];
__device__ float g_hidden[TOK * HID];

// ---------------- helpers ----------------
__device__ __forceinline__ uint32_t f2tf(float v) {
    uint32_t r;
    asm("cvt.rna.tf32.f32 %0, %1;" : "=r"(r) : "f"(v));
    return r;
}
__device__ __forceinline__ void mma8(float* c, const uint32_t* a, const uint32_t* b) {
    asm volatile(
        "mma.sync.aligned.m16n8k8.row.col.f32.tf32.tf32.f32 "
        "{%0,%1,%2,%3}, {%4,%5,%6,%7}, {%8,%9}, {%0,%1,%2,%3};"
        : "+f"(c[0]), "+f"(c[1]), "+f"(c[2]), "+f"(c[3])
        : "r"(a[0]), "r"(a[1]), "r"(a[2]), "r"(a[3]), "r"(b[0]), "r"(b[1]));
}
__device__ __forceinline__ void ldsm4(uint32_t* r, const float* p) {
    uint32_t a = (uint32_t)__cvta_generic_to_shared(p);
    asm volatile("ldmatrix.sync.aligned.m8n8.x4.shared.b16 {%0,%1,%2,%3}, [%4];"
                 : "=r"(r[0]), "=r"(r[1]), "=r"(r[2]), "=r"(r[3]) : "r"(a));
}
__device__ __forceinline__ void cp16(void* smem, const void* g) {
    uint32_t a = (uint32_t)__cvta_generic_to_shared(smem);
    asm volatile("cp.async.cg.shared.global [%0], [%1], 16;" :: "r"(a), "l"(g));
}
__device__ __forceinline__ void cp_commit() { asm volatile("cp.async.commit_group;"); }
template <int N>
__device__ __forceinline__ void cp_wait() { asm volatile("cp.async.wait_group %0;" :: "n"(N)); }

#define CE(x, y) { float _hi = fmaxf(x, y), _lo = fminf(x, y); x = _hi; y = _lo; }

// ---------------- LN1: (B,C,H,W) -> window-major token rows, normalized --------
__global__ void ln1_kernel(const float* __restrict__ x,
                           const float* __restrict__ g,
                           const float* __restrict__ bt) {
    __shared__ float s[CDIM][33];
    __shared__ float s_mu[32], s_rs[32];
    int tile = blockIdx.x;
    int b = tile / (LTOK / 32);
    int l0 = (tile % (LTOK / 32)) * 32;
    const float* xb = x + (size_t)b * CDIM * LTOK;
    for (int idx = threadIdx.x; idx < CDIM * 32; idx += 256) {
        int c = idx >> 5, i = idx & 31;
        s[c][i] = xb[(size_t)c * LTOK + l0 + i];
    }
    __syncthreads();
    int warp = threadIdx.x >> 5, lane = threadIdx.x & 31;
    for (int i = warp; i < 32; i += 8) {
        float sum = 0.f, ss = 0.f;
        #pragma unroll
        for (int j = 0; j < 6; j++) {
            float v = s[j * 32 + lane][i];
            sum += v; ss += v * v;
        }
        #pragma unroll
        for (int o = 16; o; o >>= 1) {
            sum += __shfl_xor_sync(~0u, sum, o);
            ss  += __shfl_xor_sync(~0u, ss, o);
        }
        float mu = sum * (1.f / CDIM);
        float var = ss * (1.f / CDIM) - mu * mu;
        if (lane == 0) { s_mu[i] = mu; s_rs[i] = rsqrtf(var + 1e-5f); }
    }
    __syncthreads();
    // window-major row: m = (b*64 + wy*8+wx)*64 + iy*8+ix
    int y = l0 >> 6, x0 = l0 & 63;
    int wybase = (b * 64 + (y >> 3) * 8) * 64 + (y & 7) * 8;  // + wx*64 + ix
    for (int idx = threadIdx.x; idx < 32 * CDIM; idx += 256) {
        int i = idx / CDIM, c = idx % CDIM;
        int xx = x0 + i;
        int row = wybase + (xx >> 3) * 64 + (xx & 7);
        g_shortcut[(size_t)row * CDIM + c] = (s[c][i] - s_mu[i]) * s_rs[i] * g[c] + bt[c];
    }
}

// ---------------- pipelined tensor-core GEMM, ldmatrix fragments -------------
// EPI: 0 plain, 1 gelu, 2 +R, 3 +R transposed (window-major m -> B,C,L),
//      4 per-32col-head l2norm.
// SPLIT: 3xTF32 hi/lo (fp32-accurate); plain path uses rna-rounded tf32.
template <int EPI, bool SPLIT>
__global__ void __launch_bounds__(256)
tgemm(const float* __restrict__ A, const float* __restrict__ Wt,
      const float* __restrict__ bias, const float* __restrict__ R,
      float* __restrict__ Cout, int M, int Nn, int K) {
    constexpr int BM = 128, BN = 64, BK = 16, ST = 20, STG = 3;
    __shared__ float As[STG][BM * ST];
    __shared__ float Bs[STG][BN * ST];

    int bm = blockIdx.x * BM, bn = blockIdx.y * BN;
    int tid = threadIdx.x, lane = tid & 31, warp = tid >> 5;
    int wm = (warp >> 1) * 32, wn = (warp & 1) * 32;
    int g = lane >> 2, tg = lane & 3;
    int l15 = lane & 15, lhi = lane >> 4;
    int l7 = (lane & 7) + 8 * (lane >> 4);
    int bko = 4 * ((lane >> 3) & 1);

    float acc[2][4][4] = {};
    int KT = K / BK;

    auto load_stage = [&](int s, int k0) {
        #pragma unroll
        for (int t = tid; t < BM * (BK / 4); t += 256) {
            int row = t >> 2, c4 = t & 3;
            cp16(&As[s][row * ST + c4 * 4], A + (size_t)(bm + row) * K + k0 + c4 * 4);
        }
        {
            int row = tid >> 2, c4 = tid & 3;
            cp16(&Bs[s][row * ST + c4 * 4], Wt + (size_t)(bn + row) * K + k0 + c4 * 4);
        }
    };

    #pragma unroll
    for (int s = 0; s < STG - 1; s++) {
        if (s < KT) load_stage(s, s * BK);
        cp_commit();
    }

    for (int kt = 0; kt < KT; kt++) {
        cp_wait<STG - 2>();
        __syncthreads();
        int pf = kt + STG - 1;
        if (pf < KT) load_stage(pf % STG, pf * BK);
        cp_commit();

        const float* as = As[kt % STG];
        const float* bs = Bs[kt % STG];
        #pragma unroll
        for (int ks = 0; ks < 2; ks++) {
            int k = ks * 8;
            uint32_t ar[2][4], br[2][4];
            #pragma unroll
            for (int mi = 0; mi < 2; mi++)
                ldsm4(ar[mi], &as[(wm + mi * 16 + l15) * ST + k + 4 * lhi]);
            #pragma unroll
            for (int nb = 0; nb < 2; nb++)
                ldsm4(br[nb], &bs[(wn + nb * 16 + l7) * ST + k + bko]);

            uint32_t ah[2][4], al[2][4], bh[2][4], bl[2][4];
            if (SPLIT) {
                #pragma unroll
                for (int mi = 0; mi < 2; mi++)
                    #pragma unroll
                    for (int j = 0; j < 4; j++) {
                        float v = __uint_as_float(ar[mi][j]);
                        ah[mi][j] = f2tf(v);
                        al[mi][j] = f2tf(v - __uint_as_float(ah[mi][j]));
                    }
                #pragma unroll
                for (int nb = 0; nb < 2; nb++)
                    #pragma unroll
                    for (int j = 0; j < 4; j++) {
                        float v = __uint_as_float(br[nb][j]);
                        bh[nb][j] = f2tf(v);
                        bl[nb][j] = f2tf(v - __uint_as_float(bh[nb][j]));
                    }
            } else {
                #pragma unroll
                for (int mi = 0; mi < 2; mi++)
                    #pragma unroll
                    for (int j = 0; j < 4; j++)
                        ah[mi][j] = f2tf(__uint_as_float(ar[mi][j]));
                #pragma unroll
                for (int nb = 0; nb < 2; nb++)
                    #pragma unroll
                    for (int j = 0; j < 4; j++)
                        bh[nb][j] = f2tf(__uint_as_float(br[nb][j]));
            }
            #pragma unroll
            for (int mi = 0; mi < 2; mi++)
                #pragma unroll
                for (int ni = 0; ni < 4; ni++) {
                    int nb = ni >> 1, e = (ni & 1) * 2;
                    uint32_t b2h[2] = {bh[nb][e], bh[nb][e + 1]};
                    mma8(acc[mi][ni], ah[mi], b2h);
                    if (SPLIT) {
                        uint32_t b2l[2] = {bl[nb][e], bl[nb][e + 1]};
                        mma8(acc[mi][ni], ah[mi], b2l);
                        mma8(acc[mi][ni], al[mi], b2h);
                    }
                }
        }
    }

    // epilogue
    if (EPI == 4) {
        #pragma unroll
        for (int mi = 0; mi < 2; mi++)
            #pragma unroll
            for (int rr = 0; rr < 2; rr++) {
                int m = bm + wm + mi * 16 + g + rr * 8;
                float v[8];
                #pragma unroll
                for (int ni = 0; ni < 4; ni++) {
                    int c = bn + wn + ni * 8 + tg * 2;
                    v[ni * 2]     = acc[mi][ni][rr * 2]     + bias[c];
                    v[ni * 2 + 1] = acc[mi][ni][rr * 2 + 1] + bias[c + 1];
                }
                float sq = 0.f;
                #pragma unroll
                for (int j = 0; j < 8; j++) sq += v[j] * v[j];
                sq += __shfl_xor_sync(~0u, sq, 1);
                sq += __shfl_xor_sync(~0u, sq, 2);
                float sc = 1.f / fmaxf(sqrtf(sq), 1e-12f);
                #pragma unroll
                for (int ni = 0; ni < 4; ni++) {
                    int c = bn + wn + ni * 8 + tg * 2;
                    Cout[(size_t)m * Nn + c]     = v[ni * 2] * sc;
                    Cout[(size_t)m * Nn + c + 1] = v[ni * 2 + 1] * sc;
                }
            }
    } else {
        #pragma unroll
        for (int mi = 0; mi < 2; mi++) {
            #pragma unroll
            for (int ni = 0; ni < 4; ni++) {
                int r0 = bm + wm + mi * 16 + g;
                int c = bn + wn + ni * 8 + tg * 2;
                float bz0 = bias[c], bz1 = bias[c + 1];
                #pragma unroll
                for (int rr = 0; rr < 2; rr++) {
                    int m = r0 + rr * 8;
                    float v0 = acc[mi][ni][rr * 2 + 0] + bz0;
                    float v1 = acc[mi][ni][rr * 2 + 1] + bz1;
                    if (EPI == 1) {
                        v0 = 0.5f * v0 * (1.f + erff(v0 * 0.70710678118654752f));
                        v1 = 0.5f * v1 * (1.f + erff(v1 * 0.70710678118654752f));
                    }
                    if (EPI == 2 || EPI == 3) {
                        v0 += R[(size_t)m * Nn + c];
                        v1 += R[(size_t)m * Nn + c + 1];
                    }
                    if (EPI == 3) {
                        // window-major m -> (b, l)
                        int b = m >> 12;
                        int l = ((m >> 9) & 7) * 512 + ((m >> 3) & 7) * 64
                              + ((m >> 6) & 7) * 8 + (m & 7);
                        Cout[((size_t)b * CDIM + c) * LTOK + l] = v0;
                        Cout[((size_t)b * CDIM + c + 1) * LTOK + l] = v1;
                    } else {
                        Cout[(size_t)m * Nn + c] = v0;
                        Cout[(size_t)m * Nn + c + 1] = v1;
                    }
                }
            }
        }
    }
}

// ---------------- tensor-core window attention: block per (window, head) -----
// Tokens are window-major: window win owns rows [win*64, win*64+64).
__global__ void __launch_bounds__(256) attn_kernel(const float* __restrict__ rpb_table,
                                                   const float* __restrict__ temperature) {
    __shared__ float qs[NW * 36], ks[NW * 36];
    __shared__ float vst[HD * 68];       // V transposed: [d][key]
    __shared__ float at[NW * 68];        // V staging, then S / P
    __shared__ float kths[NW], maxs[NW];
    int win = blockIdx.x, h = blockIdx.y;
    int tid = threadIdx.x, lane = tid & 31, warp = tid >> 5;
    int g = lane >> 2, tg = lane & 3;
    int l15 = lane & 15, lhi = lane >> 4;
    int l7 = (lane & 7) + 8 * (lane >> 4);
    int bko = 4 * ((lane >> 3) & 1);

    // linear loads: q,k (pre-normalized) + v staged into at
    const float* qbase = g_qkv + (size_t)win * NW * (3 * CDIM) + h * HD;
    for (int idx = tid; idx < NW * HD; idx += 256) {
        int n = idx >> 5, d = idx & 31;
        const float* base = qbase + n * (3 * CDIM) + d;
        qs[n * 36 + d] = base[0];
        ks[n * 36 + d] = base[CDIM];
        at[n * 68 + d] = base[2 * CDIM];
    }
    __syncthreads();

    // transpose v: at[n][d] -> vst[d][n]
    for (int idx = tid; idx < NW * HD; idx += 256) {
        int n = idx & 63, d = idx >> 6;
        vst[d * 68 + n] = at[n * 68 + d];
    }
    __syncthreads();

    float temp = temperature[h];
    // S mma: warp tile m16 x n32 (split-3xTF32)
    {
        int wm = (warp >> 1) * 16, wn = (warp & 1) * 32;
        float acc[4][4] = {};
        #pragma unroll
        for (int kc = 0; kc < 4; kc++) {
            int k = kc * 8;
            uint32_t ar[4], br[2][4];
            ldsm4(ar, &qs[(wm + l15) * 36 + k + 4 * lhi]);
            #pragma unroll
            for (int nb = 0; nb < 2; nb++)
                ldsm4(br[nb], &ks[(wn + nb * 16 + l7) * 36 + k + bko]);
            uint32_t ah[4], al[4], bh[2][4], bl[2][4];
            #pragma unroll
            for (int j = 0; j < 4; j++) {
                float v = __uint_as_float(ar[j]);
                ah[j] = f2tf(v);
                al[j] = f2tf(v - __uint_as_float(ah[j]));
            }
            #pragma unroll
            for (int nb = 0; nb < 2; nb++)
                #pragma unroll
                for (int j = 0; j < 4; j++) {
                    float v = __uint_as_float(br[nb][j]);
                    bh[nb][j] = f2tf(v);
                    bl[nb][j] = f2tf(v - __uint_as_float(bh[nb][j]));
                }
            #pragma unroll
            for (int ni = 0; ni < 4; ni++) {
                int nb = ni >> 1, e = (ni & 1) * 2;
                uint32_t b2h[2] = {bh[nb][e], bh[nb][e + 1]};
                uint32_t b2l[2] = {bl[nb][e], bl[nb][e + 1]};
                mma8(acc[ni], ah, b2h);
                mma8(acc[ni], ah, b2l);
                mma8(acc[ni], al, b2h);
            }
        }
        #pragma unroll
        for (int ni = 0; ni < 4; ni++) {
            float* p0 = &at[(wm + g) * 68 + wn + ni * 8 + tg * 2];
            float* p1 = &at[(wm + g + 8) * 68 + wn + ni * 8 + tg * 2];
            p0[0] = acc[ni][0] * temp; p0[1] = acc[ni][1] * temp;
            p1[0] = acc[ni][2] * temp; p1[1] = acc[ni][3] * temp;
        }
    }
    __syncthreads();

    // top-16 threshold: 8 lanes/row; per-lane Batcher-sorted queues + 16 merges
    {
        int group = lane >> 3, pos = lane & 7;
        unsigned gmask = 0xFFu << (group * 8);
        #pragma unroll
        for (int rb = 0; rb < 2; rb++) {
            int row = warp + 8 * (rb * 4 + group);
            const float* rp = &at[row * 68 + pos];
            float a0 = rp[0],  a1 = rp[8],  a2 = rp[16], a3 = rp[24];
            float a4 = rp[32], a5 = rp[40], a6 = rp[48], a7 = rp[56];
            CE(a0, a1); CE(a2, a3); CE(a4, a5); CE(a6, a7);
            CE(a0, a2); CE(a1, a3); CE(a4, a6); CE(a5, a7);
            CE(a1, a2); CE(a5, a6);
            CE(a0, a4); CE(a1, a5); CE(a2, a6); CE(a3, a7);
            CE(a2, a4); CE(a3, a5);
            CE(a1, a2); CE(a3, a4); CE(a5, a6);
            float hd = a0, kth = 0.f, mx0 = 0.f;
            #pragma unroll
            for (int it = 0; it < INCC; it++) {
                float gm = hd;
                gm = fmaxf(gm, __shfl_xor_sync(~0u, gm, 4));
                gm = fmaxf(gm, __shfl_xor_sync(~0u, gm, 2));
                gm = fmaxf(gm, __shfl_xor_sync(~0u, gm, 1));
                if (it == 0) mx0 = gm;
                kth = gm;
                unsigned bal = __ballot_sync(~0u, hd == gm) & gmask;
                if (lane == __ffs(bal) - 1) {
                    a0 = a1; a1 = a2; a2 = a3; a3 = a4;
                    a4 = a5; a5 = a6; a6 = a7; a7 = -1e30f;
                    hd = a0;
                }
            }
            if (pos == 0) { kths[row] = kth; maxs[row] = mx0; }
        }
    }
    __syncthreads();

    // per-row: mask below kth, +rpb, softmax shifted by row max0
    {
        int jy = lane >> 3, jx = lane & 7;
        int off0 = ((7 - jy) * 15 + (7 - jx)) * HEADS;
        int off1 = ((3 - jy) * 15 + (7 - jx)) * HEADS;
        for (int r = warp; r < NW; r += 8) {
            float a0 = at[r * 68 + lane], a1 = at[r * 68 + lane + 32];
            float kth = kths[r], m = maxs[r];
            int base = ((r >> 3) * 15 + (r & 7)) * HEADS + h;
            float v0 = (a0 >= kth ? a0 : -100.f) + rpb_table[base + off0];
            float v1 = (a1 >= kth ? a1 : -100.f) + rpb_table[base + off1];
            float e0 = __expf(v0 - m), e1 = __expf(v1 - m);
            float s = e0 + e1;
            #pragma unroll
            for (int o = 16; o; o >>= 1) s += __shfl_xor_sync(~0u, s, o);
            float inv = 1.f / s;
            at[r * 68 + lane] = e0 * inv;
            at[r * 68 + lane + 32] = e1 * inv;
        }
    }
    __syncthreads();

    // O = P @ V : warp tile m16 x n16, k=64; linear window-major store
    {
        int mt = warp >> 1, nh = (warp & 1) * 16;
        float acc[2][4] = {};
        #pragma unroll
        for (int kc = 0; kc < 8; kc++) {
            int k = kc * 8;
            uint32_t ar[4], br[4], af[4], bf[4];
            ldsm4(ar, &at[(mt * 16 + l15) * 68 + k + 4 * lhi]);
            ldsm4(br, &vst[(nh + l7) * 68 + k + bko]);
            #pragma unroll
            for (int j = 0; j < 4; j++) {
                af[j] = f2tf(__uint_as_float(ar[j]));
                bf[j] = f2tf(__uint_as_float(br[j]));
            }
            uint32_t b20[2] = {bf[0], bf[1]};
            uint32_t b21[2] = {bf[2], bf[3]};
            mma8(acc[0], af, b20);
            mma8(acc[1], af, b21);
        }
        float* obase = g_attnout + (size_t)win * NW * CDIM + h * HD;
        #pragma unroll
        for (int ni = 0; ni < 2; ni++) {
            int c = nh + ni * 8 + tg * 2;
            #pragma unroll
            for (int rr = 0; rr < 2; rr++) {
                int m = mt * 16 + g + rr * 8;
                obase[(size_t)m * CDIM + c]     = acc[ni][rr * 2];
                obase[(size_t)m * CDIM + c + 1] = acc[ni][rr * 2 + 1];
            }
        }
    }
}

// ---------------- LN2 ----------------
__global__ void ln2_kernel(const float* __restrict__ xin,
                           const float* __restrict__ g,
                           const float* __restrict__ bt,
                           float* __restrict__ out) {
    int t = blockIdx.x * 8 + (threadIdx.x >> 5);
    int lane = threadIdx.x & 31;
    const float* row = xin + (size_t)t * CDIM;
    float v[6]; float sum = 0.f, ss = 0.f;
    #pragma unroll
    for (int j = 0; j < 6; j++) {
        v[j] = row[j * 32 + lane];
        sum += v[j]; ss += v[j] * v[j];
    }
    #pragma unroll
    for (int o = 16; o; o >>= 1) {
        sum += __shfl_xor_sync(~0u, sum, o);
        ss  += __shfl_xor_sync(~0u, ss, o);
    }
    float mu = sum * (1.f / CDIM);
    float rs = rsqrtf(ss * (1.f / CDIM) - mu * mu + 1e-5f);
    float* orow = out + (size_t)t * CDIM;
    #pragma unroll
    for (int j = 0; j < 6; j++) {
        int c = j * 32 + lane;
        orow[c] = (v[j] - mu) * rs * g[c] + bt[c];
    }
}

// ---------------- launch ----------------
extern "C" void kernel_launch(void* const* d_in, const int* in_sizes, int n_in,
                              void* d_out, int out_size) {
    const float* x       = (const float*)d_in[0];
    const float* norm1_g = (const float*)d_in[1];
    const float* norm1_b = (const float*)d_in[2];
    const float* qkv_w   = (const float*)d_in[3];
    const float* qkv_b   = (const float*)d_in[4];
    const float* proj_w  = (const float*)d_in[5];
    const float* proj_b  = (const float*)d_in[6];
    const float* rpb     = (const float*)d_in[7];
    const float* temp    = (const float*)d_in[8];
    const float* norm2_g = (const float*)d_in[9];
    const float* norm2_b = (const float*)d_in[10];
    const float* fc1_w   = (const float*)d_in[11];
    const float* fc1_b   = (const float*)d_in[12];
    const float* fc2_w   = (const float*)d_in[13];
    const float* fc2_b   = (const float*)d_in[14];
    float* out = (float*)d_out;

    float *p_shortcut, *p_qkv, *p_attnout, *p_x2, *p_ln2, *p_hidden;
    cudaGetSymbolAddress((void**)&p_shortcut, g_shortcut);
    cudaGetSymbolAddress((void**)&p_qkv,      g_qkv);
    cudaGetSymbolAddress((void**)&p_attnout,  g_attnout);
    cudaGetSymbolAddress((void**)&p_x2,       g_x2);
    cudaGetSymbolAddress((void**)&p_ln2,      g_ln2);
    cudaGetSymbolAddress((void**)&p_hidden,   g_hidden);

    // 1) LN1 (+ NCHW -> window-major token rows)
    ln1_kernel<<<TOK / 32, 256>>>(x, norm1_g, norm1_b);

    // 2a) Q,K projection: cols 0..383, 3xTF32 split + fused per-head l2norm
    tgemm<4, true><<<dim3(TOK / 128, 384 / 64), 256>>>(
        p_shortcut, qkv_w, qkv_b, nullptr, p_qkv, TOK, 576, CDIM);
    // 2b) V projection: cols 384..575, plain rna-tf32
    tgemm<0, false><<<dim3(TOK / 128, 192 / 64), 256>>>(
        p_shortcut, qkv_w + 384 * CDIM, qkv_b + 384, nullptr, p_qkv + 384,
        TOK, 576, CDIM);

    // 3) windowed attention (tensor-core, linear window-major addressing)
    attn_kernel<<<dim3(NWIN, HEADS), 256>>>(rpb, temp);

    // 4) proj + residual(shortcut) -> x2
    tgemm<2, false><<<dim3(TOK / 128, CDIM / 64), 256>>>(
        p_attnout, proj_w, proj_b, p_shortcut, p_x2, TOK, CDIM, CDIM);

    // 5) LN2
    ln2_kernel<<<TOK / 8, 256>>>(p_x2, norm2_g, norm2_b, p_ln2);

    // 6) fc1 + gelu
    tgemm<1, false><<<dim3(TOK / 128, HID / 64), 256>>>(
        p_ln2, fc1_w, fc1_b, nullptr, p_hidden, TOK, HID, CDIM);

    // 7) fc2 + residual(x2), fused un-permuting transpose to (B,C,L)
    tgemm<3, false><<<dim3(TOK / 128, CDIM / 64), 256>>>(
        p_hidden, fc2_w, fc2_b, p_x2, out, TOK, CDIM, HID);
}

// round 15
// speedup vs baseline: 1.0248x; 1.0248x over previous
#include <cuda_runtime.h>
#include <math.h>
#include <stdint.h>

// ---------------- problem constants ----------------
#define BATCH 8
#define CDIM 192
#define HH 64
#define WW 64
#define LTOK 4096
#define TOK 32768
#define HEADS 6
#define HD 32
#define WS 8
#define NW 64
#define NWIN 512
#define INCC 16
#define HID 768

// ---------------- scratch (all token-major tensors in WINDOW-MAJOR row order) --
__device__ float g_shortcut[TOK * CDIM];
__device__ float g_qkv[TOK * 3 * CDIM];
__device__ float g_attnout[TOK * CDIM];
__device__ float g_x2[TOK * CDIM];
__device__ float g_ln2[TOK * CDIM];
__device__ float g_hidden[TOK * HID];

// ---------------- helpers ----------------
// f2tf / mma8 are PURE register ops: non-volatile so ptxas can schedule them
// into ldmatrix latency holes.
__device__ __forceinline__ uint32_t f2tf(float v) {
    uint32_t r;
    asm("cvt.rna.tf32.f32 %0, %1;" : "=r"(r) : "f"(v));
    return r;
}
__device__ __forceinline__ void mma8(float* c, const uint32_t* a, const uint32_t* b) {
    asm("mma.sync.aligned.m16n8k8.row.col.f32.tf32.tf32.f32 "
        "{%0,%1,%2,%3}, {%4,%5,%6,%7}, {%8,%9}, {%0,%1,%2,%3};"
        : "+f"(c[0]), "+f"(c[1]), "+f"(c[2]), "+f"(c[3])
        : "r"(a[0]), "r"(a[1]), "r"(a[2]), "r"(a[3]), "r"(b[0]), "r"(b[1]));
}
__device__ __forceinline__ void ldsm4(uint32_t* r, const float* p) {
    uint32_t a = (uint32_t)__cvta_generic_to_shared(p);
    asm volatile("ldmatrix.sync.aligned.m8n8.x4.shared.b16 {%0,%1,%2,%3}, [%4];"
                 : "=r"(r[0]), "=r"(r[1]), "=r"(r[2]), "=r"(r[3]) : "r"(a));
}
__device__ __forceinline__ void cp16(void* smem, const void* g) {
    uint32_t a = (uint32_t)__cvta_generic_to_shared(smem);
    asm volatile("cp.async.cg.shared.global [%0], [%1], 16;" :: "r"(a), "l"(g));
}
__device__ __forceinline__ void cp_commit() { asm volatile("cp.async.commit_group;"); }
template <int N>
__device__ __forceinline__ void cp_wait() { asm volatile("cp.async.wait_group %0;" :: "n"(N)); }

#define CE(x, y) { float _hi = fmaxf(x, y), _lo = fminf(x, y); x = _hi; y = _lo; }

// ---------------- LN1: (B,C,H,W) -> window-major token rows, normalized --------
__global__ void ln1_kernel(const float* __restrict__ x,
                           const float* __restrict__ g,
                           const float* __restrict__ bt) {
    __shared__ float s[CDIM][33];
    __shared__ float s_mu[32], s_rs[32];
    int tile = blockIdx.x;
    int b = tile / (LTOK / 32);
    int l0 = (tile % (LTOK / 32)) * 32;
    const float* xb = x + (size_t)b * CDIM * LTOK;
    for (int idx = threadIdx.x; idx < CDIM * 32; idx += 256) {
        int c = idx >> 5, i = idx & 31;
        s[c][i] = xb[(size_t)c * LTOK + l0 + i];
    }
    __syncthreads();
    int warp = threadIdx.x >> 5, lane = threadIdx.x & 31;
    for (int i = warp; i < 32; i += 8) {
        float sum = 0.f, ss = 0.f;
        #pragma unroll
        for (int j = 0; j < 6; j++) {
            float v = s[j * 32 + lane][i];
            sum += v; ss += v * v;
        }
        #pragma unroll
        for (int o = 16; o; o >>= 1) {
            sum += __shfl_xor_sync(~0u, sum, o);
            ss  += __shfl_xor_sync(~0u, ss, o);
        }
        float mu = sum * (1.f / CDIM);
        float var = ss * (1.f / CDIM) - mu * mu;
        if (lane == 0) { s_mu[i] = mu; s_rs[i] = rsqrtf(var + 1e-5f); }
    }
    __syncthreads();
    // window-major row: m = (b*64 + wy*8+wx)*64 + iy*8+ix
    int y = l0 >> 6, x0 = l0 & 63;
    int wybase = (b * 64 + (y >> 3) * 8) * 64 + (y & 7) * 8;
    for (int idx = threadIdx.x; idx < 32 * CDIM; idx += 256) {
        int i = idx / CDIM, c = idx % CDIM;
        int xx = x0 + i;
        int row = wybase + (xx >> 3) * 64 + (xx & 7);
        g_shortcut[(size_t)row * CDIM + c] = (s[c][i] - s_mu[i]) * s_rs[i] * g[c] + bt[c];
    }
}

// ---------------- pipelined tensor-core GEMM, ldmatrix fragments -------------
// EPI: 0 plain, 1 gelu, 2 +R, 3 +R transposed (window-major m -> B,C,L),
//      4 per-32col-head l2norm.
// SPLIT: 3xTF32 hi/lo (fp32-accurate); plain path uses rna-rounded tf32.
// Per-kt: ALL 8 ldmatrix issued upfront so chunk-1 loads overlap chunk-0 MMAs.
template <int EPI, bool SPLIT>
__global__ void __launch_bounds__(256)
tgemm(const float* __restrict__ A, const float* __restrict__ Wt,
      const float* __restrict__ bias, const float* __restrict__ R,
      float* __restrict__ Cout, int M, int Nn, int K) {
    constexpr int BM = 128, BN = 64, BK = 16, ST = 20, STG = 3;
    __shared__ float As[STG][BM * ST];
    __shared__ float Bs[STG][BN * ST];

    int bm = blockIdx.x * BM, bn = blockIdx.y * BN;
    int tid = threadIdx.x, lane = tid & 31, warp = tid >> 5;
    int wm = (warp >> 1) * 32, wn = (warp & 1) * 32;
    int g = lane >> 2, tg = lane & 3;
    int l15 = lane & 15, lhi = lane >> 4;
    int l7 = (lane & 7) + 8 * (lane >> 4);
    int bko = 4 * ((lane >> 3) & 1);

    float acc[2][4][4] = {};
    int KT = K / BK;

    auto load_stage = [&](int s, int k0) {
        #pragma unroll
        for (int t = tid; t < BM * (BK / 4); t += 256) {
            int row = t >> 2, c4 = t & 3;
            cp16(&As[s][row * ST + c4 * 4], A + (size_t)(bm + row) * K + k0 + c4 * 4);
        }
        {
            int row = tid >> 2, c4 = tid & 3;
            cp16(&Bs[s][row * ST + c4 * 4], Wt + (size_t)(bn + row) * K + k0 + c4 * 4);
        }
    };

    #pragma unroll
    for (int s = 0; s < STG - 1; s++) {
        if (s < KT) load_stage(s, s * BK);
        cp_commit();
    }

    for (int kt = 0; kt < KT; kt++) {
        cp_wait<STG - 2>();
        __syncthreads();
        int pf = kt + STG - 1;
        if (pf < KT) load_stage(pf % STG, pf * BK);
        cp_commit();

        const float* as = As[kt % STG];
        const float* bs = Bs[kt % STG];

        // issue all fragment loads for both k-chunks up front
        uint32_t ar[2][2][4], br[2][2][4];   // [ks][mi|nb][4]
        #pragma unroll
        for (int ks = 0; ks < 2; ks++) {
            int k = ks * 8;
            #pragma unroll
            for (int mi = 0; mi < 2; mi++)
                ldsm4(ar[ks][mi], &as[(wm + mi * 16 + l15) * ST + k + 4 * lhi]);
            #pragma unroll
            for (int nb = 0; nb < 2; nb++)
                ldsm4(br[ks][nb], &bs[(wn + nb * 16 + l7) * ST + k + bko]);
        }

        #pragma unroll
        for (int ks = 0; ks < 2; ks++) {
            uint32_t ah[2][4], al[2][4], bh[2][4], bl[2][4];
            if (SPLIT) {
                #pragma unroll
                for (int mi = 0; mi < 2; mi++)
                    #pragma unroll
                    for (int j = 0; j < 4; j++) {
                        float v = __uint_as_float(ar[ks][mi][j]);
                        ah[mi][j] = f2tf(v);
                        al[mi][j] = f2tf(v - __uint_as_float(ah[mi][j]));
                    }
                #pragma unroll
                for (int nb = 0; nb < 2; nb++)
                    #pragma unroll
                    for (int j = 0; j < 4; j++) {
                        float v = __uint_as_float(br[ks][nb][j]);
                        bh[nb][j] = f2tf(v);
                        bl[nb][j] = f2tf(v - __uint_as_float(bh[nb][j]));
                    }
            } else {
                #pragma unroll
                for (int mi = 0; mi < 2; mi++)
                    #pragma unroll
                    for (int j = 0; j < 4; j++)
                        ah[mi][j] = f2tf(__uint_as_float(ar[ks][mi][j]));
                #pragma unroll
                for (int nb = 0; nb < 2; nb++)
                    #pragma unroll
                    for (int j = 0; j < 4; j++)
                        bh[nb][j] = f2tf(__uint_as_float(br[ks][nb][j]));
            }
            #pragma unroll
            for (int mi = 0; mi < 2; mi++)
                #pragma unroll
                for (int ni = 0; ni < 4; ni++) {
                    int nb = ni >> 1, e = (ni & 1) * 2;
                    uint32_t b2h[2] = {bh[nb][e], bh[nb][e + 1]};
                    mma8(acc[mi][ni], ah[mi], b2h);
                    if (SPLIT) {
                        uint32_t b2l[2] = {bl[nb][e], bl[nb][e + 1]};
                        mma8(acc[mi][ni], ah[mi], b2l);
                        mma8(acc[mi][ni], al[mi], b2h);
                    }
                }
        }
    }

    // epilogue
    if (EPI == 4) {
        #pragma unroll
        for (int mi = 0; mi < 2; mi++)
            #pragma unroll
            for (int rr = 0; rr < 2; rr++) {
                int m = bm + wm + mi * 16 + g + rr * 8;
                float v[8];
                #pragma unroll
                for (int ni = 0; ni < 4; ni++) {
                    int c = bn + wn + ni * 8 + tg * 2;
                    v[ni * 2]     = acc[mi][ni][rr * 2]     + bias[c];
                    v[ni * 2 + 1] = acc[mi][ni][rr * 2 + 1] + bias[c + 1];
                }
                float sq = 0.f;
                #pragma unroll
                for (int j = 0; j < 8; j++) sq += v[j] * v[j];
                sq += __shfl_xor_sync(~0u, sq, 1);
                sq += __shfl_xor_sync(~0u, sq, 2);
                float sc = 1.f / fmaxf(sqrtf(sq), 1e-12f);
                #pragma unroll
                for (int ni = 0; ni < 4; ni++) {
                    int c = bn + wn + ni * 8 + tg * 2;
                    Cout[(size_t)m * Nn + c]     = v[ni * 2] * sc;
                    Cout[(size_t)m * Nn + c + 1] = v[ni * 2 + 1] * sc;
                }
            }
    } else {
        #pragma unroll
        for (int mi = 0; mi < 2; mi++) {
            #pragma unroll
            for (int ni = 0; ni < 4; ni++) {
                int r0 = bm + wm + mi * 16 + g;
                int c = bn + wn + ni * 8 + tg * 2;
                float bz0 = bias[c], bz1 = bias[c + 1];
                #pragma unroll
                for (int rr = 0; rr < 2; rr++) {
                    int m = r0 + rr * 8;
                    float v0 = acc[mi][ni][rr * 2 + 0] + bz0;
                    float v1 = acc[mi][ni][rr * 2 + 1] + bz1;
                    if (EPI == 1) {
                        v0 = 0.5f * v0 * (1.f + erff(v0 * 0.70710678118654752f));
                        v1 = 0.5f * v1 * (1.f + erff(v1 * 0.70710678118654752f));
                    }
                    if (EPI == 2 || EPI == 3) {
                        v0 += R[(size_t)m * Nn + c];
                        v1 += R[(size_t)m * Nn + c + 1];
                    }
                    if (EPI == 3) {
                        int b = m >> 12;
                        int l = ((m >> 9) & 7) * 512 + ((m >> 3) & 7) * 64
                              + ((m >> 6) & 7) * 8 + (m & 7);
                        Cout[((size_t)b * CDIM + c) * LTOK + l] = v0;
                        Cout[((size_t)b * CDIM + c + 1) * LTOK + l] = v1;
                    } else {
                        Cout[(size_t)m * Nn + c] = v0;
                        Cout[(size_t)m * Nn + c + 1] = v1;
                    }
                }
            }
        }
    }
}

// ---------------- tensor-core window attention: block per (window, head) -----
// Tokens are window-major: window win owns rows [win*64, win*64+64).
__global__ void __launch_bounds__(256) attn_kernel(const float* __restrict__ rpb_table,
                                                   const float* __restrict__ temperature) {
    __shared__ float qs[NW * 36], ks[NW * 36];
    __shared__ float vst[HD * 68];       // V transposed: [d][key]
    __shared__ float at[NW * 68];        // V staging, then S / P
    __shared__ float kths[NW], maxs[NW];
    int win = blockIdx.x, h = blockIdx.y;
    int tid = threadIdx.x, lane = tid & 31, warp = tid >> 5;
    int g = lane >> 2, tg = lane & 3;
    int l15 = lane & 15, lhi = lane >> 4;
    int l7 = (lane & 7) + 8 * (lane >> 4);
    int bko = 4 * ((lane >> 3) & 1);

    // linear loads: q,k (pre-normalized) + v staged into at
    const float* qbase = g_qkv + (size_t)win * NW * (3 * CDIM) + h * HD;
    for (int idx = tid; idx < NW * HD; idx += 256) {
        int n = idx >> 5, d = idx & 31;
        const float* base = qbase + n * (3 * CDIM) + d;
        qs[n * 36 + d] = base[0];
        ks[n * 36 + d] = base[CDIM];
        at[n * 68 + d] = base[2 * CDIM];
    }
    __syncthreads();

    // transpose v: at[n][d] -> vst[d][n]
    for (int idx = tid; idx < NW * HD; idx += 256) {
        int n = idx & 63, d = idx >> 6;
        vst[d * 68 + n] = at[n * 68 + d];
    }
    __syncthreads();

    float temp = temperature[h];
    // S mma: warp tile m16 x n32 (split-3xTF32)
    {
        int wm = (warp >> 1) * 16, wn = (warp & 1) * 32;
        float acc[4][4] = {};
        #pragma unroll
        for (int kc = 0; kc < 4; kc++) {
            int k = kc * 8;
            uint32_t ar[4], br[2][4];
            ldsm4(ar, &qs[(wm + l15) * 36 + k + 4 * lhi]);
            #pragma unroll
            for (int nb = 0; nb < 2; nb++)
                ldsm4(br[nb], &ks[(wn + nb * 16 + l7) * 36 + k + bko]);
            uint32_t ah[4], al[4], bh[2][4], bl[2][4];
            #pragma unroll
            for (int j = 0; j < 4; j++) {
                float v = __uint_as_float(ar[j]);
                ah[j] = f2tf(v);
                al[j] = f2tf(v - __uint_as_float(ah[j]));
            }
            #pragma unroll
            for (int nb = 0; nb < 2; nb++)
                #pragma unroll
                for (int j = 0; j < 4; j++) {
                    float v = __uint_as_float(br[nb][j]);
                    bh[nb][j] = f2tf(v);
                    bl[nb][j] = f2tf(v - __uint_as_float(bh[nb][j]));
                }
            #pragma unroll
            for (int ni = 0; ni < 4; ni++) {
                int nb = ni >> 1, e = (ni & 1) * 2;
                uint32_t b2h[2] = {bh[nb][e], bh[nb][e + 1]};
                uint32_t b2l[2] = {bl[nb][e], bl[nb][e + 1]};
                mma8(acc[ni], ah, b2h);
                mma8(acc[ni], ah, b2l);
                mma8(acc[ni], al, b2h);
            }
        }
        #pragma unroll
        for (int ni = 0; ni < 4; ni++) {
            float* p0 = &at[(wm + g) * 68 + wn + ni * 8 + tg * 2];
            float* p1 = &at[(wm + g + 8) * 68 + wn + ni * 8 + tg * 2];
            p0[0] = acc[ni][0] * temp; p0[1] = acc[ni][1] * temp;
            p1[0] = acc[ni][2] * temp; p1[1] = acc[ni][3] * temp;
        }
    }
    __syncthreads();

    // top-16 threshold: 8 lanes/row; per-lane Batcher-sorted queues + 16 merges
    {
        int group = lane >> 3, pos = lane & 7;
        unsigned gmask = 0xFFu << (group * 8);
        #pragma unroll
        for (int rb = 0; rb < 2; rb++) {
            int row = warp + 8 * (rb * 4 + group);
            const float* rp = &at[row * 68 + pos];
            float a0 = rp[0],  a1 = rp[8],  a2 = rp[16], a3 = rp[24];
            float a4 = rp[32], a5 = rp[40], a6 = rp[48], a7 = rp[56];
            CE(a0, a1); CE(a2, a3); CE(a4, a5); CE(a6, a7);
            CE(a0, a2); CE(a1, a3); CE(a4, a6); CE(a5, a7);
            CE(a1, a2); CE(a5, a6);
            CE(a0, a4); CE(a1, a5); CE(a2, a6); CE(a3, a7);
            CE(a2, a4); CE(a3, a5);
            CE(a1, a2); CE(a3, a4); CE(a5, a6);
            float hd = a0, kth = 0.f, mx0 = 0.f;
            #pragma unroll
            for (int it = 0; it < INCC; it++) {
                float gm = hd;
                gm = fmaxf(gm, __shfl_xor_sync(~0u, gm, 4));
                gm = fmaxf(gm, __shfl_xor_sync(~0u, gm, 2));
                gm = fmaxf(gm, __shfl_xor_sync(~0u, gm, 1));
                if (it == 0) mx0 = gm;
                kth = gm;
                unsigned bal = __ballot_sync(~0u, hd == gm) & gmask;
                if (lane == __ffs(bal) - 1) {
                    a0 = a1; a1 = a2; a2 = a3; a3 = a4;
                    a4 = a5; a5 = a6; a6 = a7; a7 = -1e30f;
                    hd = a0;
                }
            }
            if (pos == 0) { kths[row] = kth; maxs[row] = mx0; }
        }
    }
    __syncthreads();

    // per-row: mask below kth, +rpb, softmax shifted by row max0
    {
        int jy = lane >> 3, jx = lane & 7;
        int off0 = ((7 - jy) * 15 + (7 - jx)) * HEADS;
        int off1 = ((3 - jy) * 15 + (7 - jx)) * HEADS;
        for (int r = warp; r < NW; r += 8) {
            float a0 = at[r * 68 + lane], a1 = at[r * 68 + lane + 32];
            float kth = kths[r], m = maxs[r];
            int base = ((r >> 3) * 15 + (r & 7)) * HEADS + h;
            float v0 = (a0 >= kth ? a0 : -100.f) + rpb_table[base + off0];
            float v1 = (a1 >= kth ? a1 : -100.f) + rpb_table[base + off1];
            float e0 = __expf(v0 - m), e1 = __expf(v1 - m);
            float s = e0 + e1;
            #pragma unroll
            for (int o = 16; o; o >>= 1) s += __shfl_xor_sync(~0u, s, o);
            float inv = 1.f / s;
            at[r * 68 + lane] = e0 * inv;
            at[r * 68 + lane + 32] = e1 * inv;
        }
    }
    __syncthreads();

    // O = P @ V : warp tile m16 x n16, k=64; linear window-major store
    {
        int mt = warp >> 1, nh = (warp & 1) * 16;
        float acc[2][4] = {};
        #pragma unroll
        for (int kc = 0; kc < 8; kc++) {
            int k = kc * 8;
            uint32_t ar[4], br[4], af[4], bf[4];
            ldsm4(ar, &at[(mt * 16 + l15) * 68 + k + 4 * lhi]);
            ldsm4(br, &vst[(nh + l7) * 68 + k + bko]);
            #pragma unroll
            for (int j = 0; j < 4; j++) {
                af[j] = f2tf(__uint_as_float(ar[j]));
                bf[j] = f2tf(__uint_as_float(br[j]));
            }
            uint32_t b20[2] = {bf[0], bf[1]};
            uint32_t b21[2] = {bf[2], bf[3]};
            mma8(acc[0], af, b20);
            mma8(acc[1], af, b21);
        }
        float* obase = g_attnout + (size_t)win * NW * CDIM + h * HD;
        #pragma unroll
        for (int ni = 0; ni < 2; ni++) {
            int c = nh + ni * 8 + tg * 2;
            #pragma unroll
            for (int rr = 0; rr < 2; rr++) {
                int m = mt * 16 + g + rr * 8;
                obase[(size_t)m * CDIM + c]     = acc[ni][rr * 2];
                obase[(size_t)m * CDIM + c + 1] = acc[ni][rr * 2 + 1];
            }
        }
    }
}

// ---------------- LN2 ----------------
__global__ void ln2_kernel(const float* __restrict__ xin,
                           const float* __restrict__ g,
                           const float* __restrict__ bt,
                           float* __restrict__ out) {
    int t = blockIdx.x * 8 + (threadIdx.x >> 5);
    int lane = threadIdx.x & 31;
    const float* row = xin + (size_t)t * CDIM;
    float v[6]; float sum = 0.f, ss = 0.f;
    #pragma unroll
    for (int j = 0; j < 6; j++) {
        v[j] = row[j * 32 + lane];
        sum += v[j]; ss += v[j] * v[j];
    }
    #pragma unroll
    for (int o = 16; o; o >>= 1) {
        sum += __shfl_xor_sync(~0u, sum, o);
        ss  += __shfl_xor_sync(~0u, ss, o);
    }
    float mu = sum * (1.f / CDIM);
    float rs = rsqrtf(ss * (1.f / CDIM) - mu * mu + 1e-5f);
    float* orow = out + (size_t)t * CDIM;
    #pragma unroll
    for (int j = 0; j < 6; j++) {
        int c = j * 32 + lane;
        orow[c] = (v[j] - mu) * rs * g[c] + bt[c];
    }
}

// ---------------- launch ----------------
extern "C" void kernel_launch(void* const* d_in, const int* in_sizes, int n_in,
                              void* d_out, int out_size) {
    const float* x       = (const float*)d_in[0];
    const float* norm1_g = (const float*)d_in[1];
    const float* norm1_b = (const float*)d_in[2];
    const float* qkv_w   = (const float*)d_in[3];
    const float* qkv_b   = (const float*)d_in[4];
    const float* proj_w  = (const float*)d_in[5];
    const float* proj_b  = (const float*)d_in[6];
    const float* rpb     = (const float*)d_in[7];
    const float* temp    = (const float*)d_in[8];
    const float* norm2_g = (const float*)d_in[9];
    const float* norm2_b = (const float*)d_in[10];
    const float* fc1_w   = (const float*)d_in[11];
    const float* fc1_b   = (const float*)d_in[12];
    const float* fc2_w   = (const float*)d_in[13];
    const float* fc2_b   = (const float*)d_in[14];
    float* out = (float*)d_out;

    float *p_shortcut, *p_qkv, *p_attnout, *p_x2, *p_ln2, *p_hidden;
    cudaGetSymbolAddress((void**)&p_shortcut, g_shortcut);
    cudaGetSymbolAddress((void**)&p_qkv,      g_qkv);
    cudaGetSymbolAddress((void**)&p_attnout,  g_attnout);
    cudaGetSymbolAddress((void**)&p_x2,       g_x2);
    cudaGetSymbolAddress((void**)&p_ln2,      g_ln2);
    cudaGetSymbolAddress((void**)&p_hidden,   g_hidden);

    // 1) LN1 (+ NCHW -> window-major token rows)
    ln1_kernel<<<TOK / 32, 256>>>(x, norm1_g, norm1_b);

    // 2a) Q,K projection: cols 0..383, 3xTF32 split + fused per-head l2norm
    tgemm<4, true><<<dim3(TOK / 128, 384 / 64), 256>>>(
        p_shortcut, qkv_w, qkv_b, nullptr, p_qkv, TOK, 576, CDIM);
    // 2b) V projection: cols 384..575, plain rna-tf32
    tgemm<0, false><<<dim3(TOK / 128, 192 / 64), 256>>>(
        p_shortcut, qkv_w + 384 * CDIM, qkv_b + 384, nullptr, p_qkv + 384,
        TOK, 576, CDIM);

    // 3) windowed attention (tensor-core, linear window-major addressing)
    attn_kernel<<<dim3(NWIN, HEADS), 256>>>(rpb, temp);

    // 4) proj + residual(shortcut) -> x2
    tgemm<2, false><<<dim3(TOK / 128, CDIM / 64), 256>>>(
        p_attnout, proj_w, proj_b, p_shortcut, p_x2, TOK, CDIM, CDIM);

    // 5) LN2
    ln2_kernel<<<TOK / 8, 256>>>(p_x2, norm2_g, norm2_b, p_ln2);

    // 6) fc1 + gelu
    tgemm<1, false><<<dim3(TOK / 128, HID / 64), 256>>>(
        p_ln2, fc1_w, fc1_b, nullptr, p_hidden, TOK, HID, CDIM);

    // 7) fc2 + residual(x2), fused un-permuting transpose to (B,C,L)
    tgemm<3, false><<<dim3(TOK / 128, CDIM / 64), 256>>>(
        p_hidden, fc2_w, fc2_b, p_x2, out, TOK, CDIM, HID);
}